// round 3
// baseline (speedup 1.0000x reference)
#include <cuda_runtime.h>
#include <math.h>

#define NPTS 131072
#define NC 4096

// ---------------- scratch (device globals) ----------------------------------
__device__ int g_cell_of[NPTS];
__device__ int g_sorted[NPTS];
__device__ float4 g_pt[2 * NPTS];    // per sorted slot: (x0,x1,x2,d0),(d1,d2,-,-)
__device__ int g_count[NC];
__device__ int g_start[NC + 1];
__device__ int g_cursor[NC];

__device__ __forceinline__ int cell_coord(float v) {
    float f = v / 0.1875f + 8.0f;
    int c = (int)f;
    if (c < 0) c = 0;
    if (c > 15) c = 15;
    return c;
}

// ---------------- pass 1: cell index + histogram ----------------------------
__global__ void k_hist(const float* __restrict__ x) {
    int p = blockIdx.x * blockDim.x + threadIdx.x;
    if (p >= NPTS) return;
    int c0 = cell_coord(x[3 * p + 0]);
    int c1 = cell_coord(x[3 * p + 1]);
    int c2 = cell_coord(x[3 * p + 2]);
    int cell = (c0 * 16 + c1) * 16 + c2;
    g_cell_of[p] = cell;
    atomicAdd(&g_count[cell], 1);
}

// ---------------- pass 2: exclusive scan + reset counts (1 block) ----------
__global__ void k_scan() {
    __shared__ int s[1024];
    int t = threadIdx.x;
    int b = t * 4;
    int c0 = g_count[b + 0];
    int c1 = g_count[b + 1];
    int c2 = g_count[b + 2];
    int c3 = g_count[b + 3];
    g_count[b + 0] = 0; g_count[b + 1] = 0; g_count[b + 2] = 0; g_count[b + 3] = 0;
    int sum = c0 + c1 + c2 + c3;
    s[t] = sum;
    __syncthreads();
    #pragma unroll
    for (int off = 1; off < 1024; off <<= 1) {
        int v = (t >= off) ? s[t - off] : 0;
        __syncthreads();
        s[t] += v;
        __syncthreads();
    }
    int excl = s[t] - sum;
    g_start[b + 0] = excl;
    g_start[b + 1] = excl + c0;
    g_start[b + 2] = excl + c0 + c1;
    g_start[b + 3] = excl + c0 + c1 + c2;
    if (t == 1023) g_start[NC] = s[1023];
}

// ---------------- pass 3: scatter indices + staged point data ---------------
__global__ void k_scatter(const float* __restrict__ x, const float* __restrict__ d) {
    int p = blockIdx.x * blockDim.x + threadIdx.x;
    if (p >= NPTS) return;
    int cell = g_cell_of[p];
    int pos = g_start[cell] + atomicAdd(&g_cursor[cell], 1);
    g_sorted[pos] = p;
    float x0 = x[3 * p + 0], x1 = x[3 * p + 1], x2 = x[3 * p + 2];
    float d0 = d[3 * p + 0], d1 = d[3 * p + 1], d2 = d[3 * p + 2];
    g_pt[2 * pos + 0] = make_float4(x0, x1, x2, d0);
    g_pt[2 * pos + 1] = make_float4(d1, d2, 0.0f, 0.0f);
}

// ---------------- fast sincos: Cody-Waite reduction + MUFU ------------------
__device__ __forceinline__ void fsincos(float a, float& sn, float& cs) {
    float k = rintf(a * 0.15915493667125702f);
    float r = fmaf(k, -6.2831854820251465f, a);
    r = fmaf(k, 1.7484556000744487e-7f, r);
    sn = __sinf(r);
    cs = __cosf(r);
}

// ---------------- pass 4: per-cell MLP, 1 warp/cell, 2 points/thread -------
template <int NO>
__device__ __forceinline__ void feed2(float v0, float v1,
                                      const float* __restrict__ w,
                                      float* a0, float* a1) {
    #pragma unroll
    for (int o = 0; o < NO; o++) {
        float wv = w[o];
        a0[o] = fmaf(v0, wv, a0[o]);
        a1[o] = fmaf(v1, wv, a1[o]);
    }
}

__global__ void __launch_bounds__(32, 8) k_mlp(
    const float* __restrict__ w1, const float* __restrict__ b1,
    const float* __restrict__ w2, const float* __restrict__ b2,
    const float* __restrict__ w3, const float* __restrict__ b3,
    const float* __restrict__ w4, const float* __restrict__ b4,
    const float* __restrict__ w5, const float* __restrict__ b5,
    float* __restrict__ out)
{
    int cell = blockIdx.x;
    int tid = threadIdx.x;

    if (tid == 0) g_cursor[cell] = 0;   // reset for next invocation

    int start = g_start[cell];
    int cnt = g_start[cell + 1] - start;
    if (cnt == 0) return;

    __shared__ __align__(16) float sw1[2016];
    __shared__ __align__(16) float sb1[32];
    __shared__ __align__(16) float sw2[32 * 36];
    __shared__ __align__(16) float sb2[36];
    __shared__ __align__(16) float sw3[1024];
    __shared__ __align__(16) float sb3[32];
    __shared__ __align__(16) float sw4[1888];
    __shared__ __align__(16) float sb4[32];
    __shared__ __align__(16) float sw5[32 * 4];
    __shared__ __align__(16) float sb5[4];

    {
        const size_t c = (size_t)cell;
        const float4* w1v = (const float4*)(w1 + c * 2016);
        const float4* w3v = (const float4*)(w3 + c * 1024);
        const float4* w4v = (const float4*)(w4 + c * 1888);
        #pragma unroll
        for (int i = 0; i < 16; i++) ((float4*)sw1)[tid + 32 * i] = w1v[tid + 32 * i];
        #pragma unroll
        for (int i = 0; i < 8; i++)  ((float4*)sw3)[tid + 32 * i] = w3v[tid + 32 * i];
        #pragma unroll
        for (int i = 0; i < 14; i++) ((float4*)sw4)[tid + 32 * i] = w4v[tid + 32 * i];
        if (tid < 472 - 32 * 14)     ((float4*)sw4)[tid + 32 * 14] = w4v[tid + 32 * 14];
        for (int i = tid; i < 1056; i += 32) {
            int r = i / 33, cc = i - r * 33;
            sw2[r * 36 + cc] = w2[c * 1056 + i];
        }
        for (int i = tid; i < 96; i += 32) {
            int r = i / 3, cc = i - r * 3;
            sw5[r * 4 + cc] = w5[c * 96 + i];
        }
        sb1[tid] = b1[c * 32 + tid];
        sb3[tid] = b3[c * 32 + tid];
        sb4[tid] = b4[c * 32 + tid];
        sb2[tid] = b2[c * 33 + tid];
        if (tid == 0) sb2[32] = b2[c * 33 + 32];
        if (tid < 3) sb5[tid] = b5[c * 3 + tid];
    }
    __syncwarp();

    for (int q0 = tid; q0 < cnt; q0 += 64) {
        int q1 = q0 + 32;
        bool has1 = q1 < cnt;
        int qs1 = has1 ? q1 : q0;

        float4 pa0 = g_pt[2 * (start + q0) + 0];
        float4 pb0 = g_pt[2 * (start + q0) + 1];
        float4 pa1 = g_pt[2 * (start + qs1) + 0];
        float4 pb1 = g_pt[2 * (start + qs1) + 1];

        float X0[3] = {pa0.x, pa0.y, pa0.z};
        float D0[3] = {pa0.w, pb0.x, pb0.y};
        float X1[3] = {pa1.x, pa1.y, pa1.z};
        float D1[3] = {pa1.w, pb1.x, pb1.y};

        bool mask0 = (fabsf(X0[0]) < 1.5f) && (fabsf(X0[1]) < 1.5f) && (fabsf(X0[2]) < 1.5f);
        bool mask1 = (fabsf(X1[0]) < 1.5f) && (fabsf(X1[1]) < 1.5f) && (fabsf(X1[2]) < 1.5f);

        float A0[33], A1[33], B0[33], B1[33];

        // ---- layer 1: encode(x) [63] -> 32, relu ----
        #pragma unroll
        for (int o = 0; o < 32; o++) { A0[o] = sb1[o]; A1[o] = A0[o]; }
        feed2<32>(X0[0], X1[0], sw1 +  0, A0, A1);
        feed2<32>(X0[1], X1[1], sw1 + 32, A0, A1);
        feed2<32>(X0[2], X1[2], sw1 + 64, A0, A1);
        {
            const float* wp = sw1 + 96;
            float s = 1.0f;
            #pragma unroll
            for (int j = 0; j < 10; j++) {
                float sn0[3], cs0[3], sn1[3], cs1[3];
                #pragma unroll
                for (int a = 0; a < 3; a++) {
                    fsincos(s * X0[a], sn0[a], cs0[a]);
                    fsincos(s * X1[a], sn1[a], cs1[a]);
                }
                feed2<32>(sn0[0], sn1[0], wp, A0, A1); wp += 32;
                feed2<32>(sn0[1], sn1[1], wp, A0, A1); wp += 32;
                feed2<32>(sn0[2], sn1[2], wp, A0, A1); wp += 32;
                feed2<32>(cs0[0], cs1[0], wp, A0, A1); wp += 32;
                feed2<32>(cs0[1], cs1[1], wp, A0, A1); wp += 32;
                feed2<32>(cs0[2], cs1[2], wp, A0, A1); wp += 32;
                s *= 2.0f;
            }
        }
        #pragma unroll
        for (int o = 0; o < 32; o++) {
            A0[o] = fmaxf(A0[o], 0.0f);
            A1[o] = fmaxf(A1[o], 0.0f);
        }

        // ---- layer 2: 32 -> 33, relu; sigma = out[0] ----
        #pragma unroll
        for (int o = 0; o < 33; o++) { B0[o] = sb2[o]; B1[o] = B0[o]; }
        #pragma unroll
        for (int i = 0; i < 32; i++) feed2<33>(A0[i], A1[i], sw2 + i * 36, B0, B1);
        #pragma unroll
        for (int o = 0; o < 33; o++) {
            B0[o] = fmaxf(B0[o], 0.0f);
            B1[o] = fmaxf(B1[o], 0.0f);
        }
        float sigma0 = B0[0], sigma1 = B1[0];

        // ---- layer 3: 32 -> 32, linear ----
        #pragma unroll
        for (int o = 0; o < 32; o++) { A0[o] = sb3[o]; A1[o] = A0[o]; }
        #pragma unroll
        for (int i = 0; i < 32; i++) feed2<32>(B0[i + 1], B1[i + 1], sw3 + i * 32, A0, A1);

        // ---- layer 4: [32 | encode(d) 27] -> 32, relu ----
        #pragma unroll
        for (int o = 0; o < 32; o++) { B0[o] = sb4[o]; B1[o] = B0[o]; }
        #pragma unroll
        for (int i = 0; i < 32; i++) feed2<32>(A0[i], A1[i], sw4 + i * 32, B0, B1);
        {
            const float* wp = sw4 + 32 * 32;
            feed2<32>(D0[0], D1[0], wp, B0, B1); wp += 32;
            feed2<32>(D0[1], D1[1], wp, B0, B1); wp += 32;
            feed2<32>(D0[2], D1[2], wp, B0, B1); wp += 32;
            float s = 1.0f;
            #pragma unroll
            for (int j = 0; j < 4; j++) {
                float sn0[3], cs0[3], sn1[3], cs1[3];
                #pragma unroll
                for (int a = 0; a < 3; a++) {
                    fsincos(s * D0[a], sn0[a], cs0[a]);
                    fsincos(s * D1[a], sn1[a], cs1[a]);
                }
                feed2<32>(sn0[0], sn1[0], wp, B0, B1); wp += 32;
                feed2<32>(sn0[1], sn1[1], wp, B0, B1); wp += 32;
                feed2<32>(sn0[2], sn1[2], wp, B0, B1); wp += 32;
                feed2<32>(cs0[0], cs1[0], wp, B0, B1); wp += 32;
                feed2<32>(cs0[1], cs1[1], wp, B0, B1); wp += 32;
                feed2<32>(cs0[2], cs1[2], wp, B0, B1); wp += 32;
                s *= 2.0f;
            }
        }
        #pragma unroll
        for (int o = 0; o < 32; o++) {
            B0[o] = fmaxf(B0[o], 0.0f);
            B1[o] = fmaxf(B1[o], 0.0f);
        }

        // ---- layer 5: 32 -> 3, sigmoid ----
        float r00 = sb5[0], r01 = sb5[1], r02 = sb5[2];
        float r10 = r00, r11 = r01, r12 = r02;
        #pragma unroll
        for (int i = 0; i < 32; i++) {
            float w0 = sw5[i * 4 + 0], w1_ = sw5[i * 4 + 1], w2_ = sw5[i * 4 + 2];
            r00 = fmaf(B0[i], w0, r00);
            r01 = fmaf(B0[i], w1_, r01);
            r02 = fmaf(B0[i], w2_, r02);
            r10 = fmaf(B1[i], w0, r10);
            r11 = fmaf(B1[i], w1_, r11);
            r12 = fmaf(B1[i], w2_, r12);
        }
        r00 = 1.0f / (1.0f + __expf(-r00));
        r01 = 1.0f / (1.0f + __expf(-r01));
        r02 = 1.0f / (1.0f + __expf(-r02));
        r10 = 1.0f / (1.0f + __expf(-r10));
        r11 = 1.0f / (1.0f + __expf(-r11));
        r12 = 1.0f / (1.0f + __expf(-r12));

        if (!mask0) { r00 = 0.0f; r01 = 0.0f; r02 = 0.0f; sigma0 = 0.0f; }
        if (!mask1) { r10 = 0.0f; r11 = 0.0f; r12 = 0.0f; sigma1 = 0.0f; }

        int idx0 = g_sorted[start + q0];
        out[3 * idx0 + 0] = r00;
        out[3 * idx0 + 1] = r01;
        out[3 * idx0 + 2] = r02;
        out[3 * NPTS + idx0] = sigma0;
        if (has1) {
            int idx1 = g_sorted[start + q1];
            out[3 * idx1 + 0] = r10;
            out[3 * idx1 + 1] = r11;
            out[3 * idx1 + 2] = r12;
            out[3 * NPTS + idx1] = sigma1;
        }
    }
}

// ---------------- launch ----------------------------------------------------
extern "C" void kernel_launch(void* const* d_in, const int* in_sizes, int n_in,
                              void* d_out, int out_size) {
    const float* x  = (const float*)d_in[0];
    const float* dd = (const float*)d_in[1];
    const float* w1 = (const float*)d_in[2];
    const float* b1 = (const float*)d_in[3];
    const float* w2 = (const float*)d_in[4];
    const float* b2 = (const float*)d_in[5];
    const float* w3 = (const float*)d_in[6];
    const float* b3 = (const float*)d_in[7];
    const float* w4 = (const float*)d_in[8];
    const float* b4 = (const float*)d_in[9];
    const float* w5 = (const float*)d_in[10];
    const float* b5 = (const float*)d_in[11];
    float* out = (float*)d_out;

    k_hist<<<NPTS / 256, 256>>>(x);
    k_scan<<<1, 1024>>>();
    k_scatter<<<NPTS / 256, 256>>>(x, dd);
    k_mlp<<<NC, 32>>>(w1, b1, w2, b2, w3, b3, w4, b4, w5, b5, out);
}

// round 4
// speedup vs baseline: 1.4631x; 1.4631x over previous
#include <cuda_runtime.h>
#include <math.h>
#include <stdint.h>

#define NPTS 131072
#define NC 4096

// ring-buffer float offsets for streamed layers
#define OFF1 0
#define OFF2 2016
#define OFF3 0
#define OFF4 1024
#define OFF5 2912
#define BUFN 3168

// ---------------- scratch (device globals) ----------------------------------
__device__ int g_cell_of[NPTS];
__device__ int g_sorted[NPTS];
__device__ float4 g_pt[2 * NPTS];     // (x0,x1,x2,d0),(d1,d2,-,-) per sorted slot
__device__ int g_count[NC];
__device__ int g_start[NC + 1];
__device__ int g_cursor[NC];
__device__ float g_w2pad[NC * 32 * 36];   // w2 rows padded 33 -> 36 (aligned)

__device__ __forceinline__ int cell_coord(float v) {
    float f = v / 0.1875f + 8.0f;
    int c = (int)f;
    if (c < 0) c = 0;
    if (c > 15) c = 15;
    return c;
}

// ---------------- prep: pad w2 rows 33 -> 36 --------------------------------
__global__ void k_pad(const float* __restrict__ w2) {
    int t = blockIdx.x * blockDim.x + threadIdx.x;
    if (t >= NC * 1056) return;
    int cell = t / 1056;
    int i = t - cell * 1056;
    int r = i / 33, c = i - r * 33;
    g_w2pad[cell * 1152 + r * 36 + c] = w2[t];
}

// ---------------- pass 1: cell index + histogram ----------------------------
__global__ void k_hist(const float* __restrict__ x) {
    int p = blockIdx.x * blockDim.x + threadIdx.x;
    if (p >= NPTS) return;
    int c0 = cell_coord(x[3 * p + 0]);
    int c1 = cell_coord(x[3 * p + 1]);
    int c2 = cell_coord(x[3 * p + 2]);
    int cell = (c0 * 16 + c1) * 16 + c2;
    g_cell_of[p] = cell;
    atomicAdd(&g_count[cell], 1);
}

// ---------------- pass 2: exclusive scan + reset counts (1 block) -----------
__global__ void k_scan() {
    __shared__ int s[1024];
    int t = threadIdx.x;
    int b = t * 4;
    int c0 = g_count[b + 0];
    int c1 = g_count[b + 1];
    int c2 = g_count[b + 2];
    int c3 = g_count[b + 3];
    g_count[b + 0] = 0; g_count[b + 1] = 0; g_count[b + 2] = 0; g_count[b + 3] = 0;
    int sum = c0 + c1 + c2 + c3;
    s[t] = sum;
    __syncthreads();
    #pragma unroll
    for (int off = 1; off < 1024; off <<= 1) {
        int v = (t >= off) ? s[t - off] : 0;
        __syncthreads();
        s[t] += v;
        __syncthreads();
    }
    int excl = s[t] - sum;
    g_start[b + 0] = excl;
    g_start[b + 1] = excl + c0;
    g_start[b + 2] = excl + c0 + c1;
    g_start[b + 3] = excl + c0 + c1 + c2;
    if (t == 1023) g_start[NC] = s[1023];
}

// ---------------- pass 3: scatter indices + staged point data ---------------
__global__ void k_scatter(const float* __restrict__ x, const float* __restrict__ d) {
    int p = blockIdx.x * blockDim.x + threadIdx.x;
    if (p >= NPTS) return;
    int cell = g_cell_of[p];
    int pos = g_start[cell] + atomicAdd(&g_cursor[cell], 1);
    g_sorted[pos] = p;
    float x0 = x[3 * p + 0], x1 = x[3 * p + 1], x2 = x[3 * p + 2];
    float d0 = d[3 * p + 0], d1 = d[3 * p + 1], d2 = d[3 * p + 2];
    g_pt[2 * pos + 0] = make_float4(x0, x1, x2, d0);
    g_pt[2 * pos + 1] = make_float4(d1, d2, 0.0f, 0.0f);
}

// ---------------- fast sincos: Cody-Waite reduction + MUFU ------------------
__device__ __forceinline__ void fsincos(float a, float& sn, float& cs) {
    float k = rintf(a * 0.15915493667125702f);
    float r = fmaf(k, -6.2831854820251465f, a);
    r = fmaf(k, 1.7484556000744487e-7f, r);
    sn = __sinf(r);
    cs = __cosf(r);
}

// ---------------- cp.async helpers ------------------------------------------
__device__ __forceinline__ void cpa16(uint32_t saddr, const void* g) {
    asm volatile("cp.async.cg.shared.global [%0], [%1], 16;" :: "r"(saddr), "l"(g));
}
__device__ __forceinline__ void cpa_commit() {
    asm volatile("cp.async.commit_group;");
}
__device__ __forceinline__ void cpa_wait0() {
    asm volatile("cp.async.wait_group 0;");
}
__device__ __forceinline__ void cpa_wait1() {
    asm volatile("cp.async.wait_group 1;");
}

template <int N4>
__device__ __forceinline__ void stage(uint32_t dst, const float4* __restrict__ src, int tid) {
    #pragma unroll
    for (int i = tid; i < N4; i += 32) cpa16(dst + 16u * i, src + i);
}

// ---------------- per-point feed --------------------------------------------
template <int NO>
__device__ __forceinline__ void feed(float v, const float* __restrict__ w, float* acc) {
    #pragma unroll
    for (int o = 0; o < NO; o++) acc[o] = fmaf(v, w[o], acc[o]);
}

// ---------------- pass 4: per-cell MLP, streamed weights, 1 warp/cell -------
__global__ void __launch_bounds__(32, 14) k_mlp(
    const float* __restrict__ w1, const float* __restrict__ b1,
    const float* __restrict__ b2,
    const float* __restrict__ w3, const float* __restrict__ b3,
    const float* __restrict__ w4, const float* __restrict__ b4,
    const float* __restrict__ w5, const float* __restrict__ b5,
    float* __restrict__ out)
{
    int cell = blockIdx.x;
    int tid = threadIdx.x;

    if (tid == 0) g_cursor[cell] = 0;   // reset for next invocation

    int start = g_start[cell];
    int cnt = g_start[cell + 1] - start;
    if (cnt == 0) return;

    __shared__ __align__(16) float sbuf[BUFN];
    __shared__ __align__(16) float sb1[32];
    __shared__ __align__(16) float sb2[36];
    __shared__ __align__(16) float sb3[32];
    __shared__ __align__(16) float sb4[32];
    __shared__ __align__(16) float sb5[4];

    const size_t c = (size_t)cell;
    const float4* w1v = (const float4*)(w1 + c * 2016);
    const float4* w2v = (const float4*)(g_w2pad + c * 1152);
    const float4* w3v = (const float4*)(w3 + c * 1024);
    const float4* w4v = (const float4*)(w4 + c * 1888);
    const float4* w5v = (const float4*)(w5 + c * 96);

    // biases once per block
    sb1[tid] = b1[c * 32 + tid];
    sb3[tid] = b3[c * 32 + tid];
    sb4[tid] = b4[c * 32 + tid];
    sb2[tid] = b2[c * 33 + tid];
    if (tid == 0) sb2[32] = b2[c * 33 + 32];
    if (tid < 3) sb5[tid] = b5[c * 3 + tid];

    uint32_t sb = (uint32_t)__cvta_generic_to_shared(sbuf);

    for (int base = 0; base < cnt; base += 32) {
        int q = base + tid;
        bool active = q < cnt;
        int slot = start + (active ? q : (cnt - 1));

        float4 pa = g_pt[2 * slot + 0];
        float4 pb = g_pt[2 * slot + 1];
        float x0 = pa.x, x1 = pa.y, x2 = pa.z;
        float d0 = pa.w, d1 = pb.x, d2 = pb.y;
        bool mask = (fabsf(x0) < 1.5f) && (fabsf(x1) < 1.5f) && (fabsf(x2) < 1.5f);

        // issue L1 and L2 prefetch
        stage<504>(sb + OFF1 * 4, w1v, tid); cpa_commit();
        stage<288>(sb + OFF2 * 4, w2v, tid); cpa_commit();
        cpa_wait1();            // L1 arrived (L2 may be pending)
        __syncwarp();

        float A[33], B[33];

        // ---- layer 1: encode(x) [63] -> 32, relu ----
        {
            const float* sw1 = sbuf + OFF1;
            #pragma unroll
            for (int o = 0; o < 32; o++) A[o] = sb1[o];
            feed<32>(x0, sw1 +  0, A);
            feed<32>(x1, sw1 + 32, A);
            feed<32>(x2, sw1 + 64, A);
            const float* wp = sw1 + 96;
            float s = 1.0f;
            #pragma unroll
            for (int j = 0; j < 10; j++) {
                float sn0, cs0, sn1, cs1, sn2, cs2;
                fsincos(s * x0, sn0, cs0);
                fsincos(s * x1, sn1, cs1);
                fsincos(s * x2, sn2, cs2);
                feed<32>(sn0, wp, A); wp += 32;
                feed<32>(sn1, wp, A); wp += 32;
                feed<32>(sn2, wp, A); wp += 32;
                feed<32>(cs0, wp, A); wp += 32;
                feed<32>(cs1, wp, A); wp += 32;
                feed<32>(cs2, wp, A); wp += 32;
                s *= 2.0f;
            }
            #pragma unroll
            for (int o = 0; o < 32; o++) A[o] = fmaxf(A[o], 0.0f);
        }

        cpa_wait0(); __syncwarp();               // L2 ready, all threads past L1
        stage<256>(sb + OFF3 * 4, w3v, tid); cpa_commit();   // prefetch L3 (over old L1)

        // ---- layer 2: 32 -> 33 (rows padded to 36), relu; sigma = out[0] ----
        {
            const float* sw2 = sbuf + OFF2;
            #pragma unroll
            for (int o = 0; o < 33; o++) B[o] = sb2[o];
            #pragma unroll
            for (int i = 0; i < 32; i++) feed<33>(A[i], sw2 + i * 36, B);
            #pragma unroll
            for (int o = 0; o < 33; o++) B[o] = fmaxf(B[o], 0.0f);
        }
        float sigma = B[0];

        cpa_wait0(); __syncwarp();               // L3 ready, all threads past L2
        stage<472>(sb + OFF4 * 4, w4v, tid); cpa_commit();   // prefetch L4

        // ---- layer 3: 32 -> 32, linear ----
        {
            const float* sw3 = sbuf + OFF3;
            #pragma unroll
            for (int o = 0; o < 32; o++) A[o] = sb3[o];
            #pragma unroll
            for (int i = 0; i < 32; i++) feed<32>(B[i + 1], sw3 + i * 32, A);
        }

        cpa_wait0(); __syncwarp();               // L4 ready
        stage<24>(sb + OFF5 * 4, w5v, tid); cpa_commit();    // prefetch L5

        // ---- layer 4: [32 | encode(d) 27] -> 32, relu ----
        {
            const float* sw4 = sbuf + OFF4;
            #pragma unroll
            for (int o = 0; o < 32; o++) B[o] = sb4[o];
            #pragma unroll
            for (int i = 0; i < 32; i++) feed<32>(A[i], sw4 + i * 32, B);
            const float* wp = sw4 + 32 * 32;
            feed<32>(d0, wp, B); wp += 32;
            feed<32>(d1, wp, B); wp += 32;
            feed<32>(d2, wp, B); wp += 32;
            float s = 1.0f;
            #pragma unroll
            for (int j = 0; j < 4; j++) {
                float sn0, cs0, sn1, cs1, sn2, cs2;
                fsincos(s * d0, sn0, cs0);
                fsincos(s * d1, sn1, cs1);
                fsincos(s * d2, sn2, cs2);
                feed<32>(sn0, wp, B); wp += 32;
                feed<32>(sn1, wp, B); wp += 32;
                feed<32>(sn2, wp, B); wp += 32;
                feed<32>(cs0, wp, B); wp += 32;
                feed<32>(cs1, wp, B); wp += 32;
                feed<32>(cs2, wp, B); wp += 32;
                s *= 2.0f;
            }
            #pragma unroll
            for (int o = 0; o < 32; o++) B[o] = fmaxf(B[o], 0.0f);
        }

        cpa_wait0(); __syncwarp();               // L5 ready

        // ---- layer 5: 32 -> 3 (raw stride 3), sigmoid ----
        float r0, r1, r2;
        {
            const float* sw5 = sbuf + OFF5;
            r0 = sb5[0]; r1 = sb5[1]; r2 = sb5[2];
            #pragma unroll
            for (int i = 0; i < 32; i++) {
                float v = B[i];
                r0 = fmaf(v, sw5[i * 3 + 0], r0);
                r1 = fmaf(v, sw5[i * 3 + 1], r1);
                r2 = fmaf(v, sw5[i * 3 + 2], r2);
            }
            r0 = 1.0f / (1.0f + __expf(-r0));
            r1 = 1.0f / (1.0f + __expf(-r1));
            r2 = 1.0f / (1.0f + __expf(-r2));
        }

        if (!mask) { r0 = 0.0f; r1 = 0.0f; r2 = 0.0f; sigma = 0.0f; }

        if (active) {
            int idx = g_sorted[start + q];
            out[3 * idx + 0] = r0;
            out[3 * idx + 1] = r1;
            out[3 * idx + 2] = r2;
            out[3 * NPTS + idx] = sigma;
        }
        __syncwarp();   // all threads done reading sbuf before next pass restages
    }
}

// ---------------- launch ----------------------------------------------------
extern "C" void kernel_launch(void* const* d_in, const int* in_sizes, int n_in,
                              void* d_out, int out_size) {
    const float* x  = (const float*)d_in[0];
    const float* dd = (const float*)d_in[1];
    const float* w1 = (const float*)d_in[2];
    const float* b1 = (const float*)d_in[3];
    const float* w2 = (const float*)d_in[4];
    const float* b2 = (const float*)d_in[5];
    const float* w3 = (const float*)d_in[6];
    const float* b3 = (const float*)d_in[7];
    const float* w4 = (const float*)d_in[8];
    const float* b4 = (const float*)d_in[9];
    const float* w5 = (const float*)d_in[10];
    const float* b5 = (const float*)d_in[11];
    float* out = (float*)d_out;

    k_pad<<<(NC * 1056 + 255) / 256, 256>>>(w2);
    k_hist<<<NPTS / 256, 256>>>(x);
    k_scan<<<1, 1024>>>();
    k_scatter<<<NPTS / 256, 256>>>(x, dd);
    k_mlp<<<NC, 32>>>(w1, b1, b2, w3, b3, w4, b4, w5, b5, out);
}

// round 5
// speedup vs baseline: 1.7752x; 1.2133x over previous
#include <cuda_runtime.h>
#include <math.h>
#include <stdint.h>

#define NPTS 131072
#define NC 4096

// ring-buffer float offsets for streamed layers
#define OFF1 0
#define OFF2 2016
#define OFF3 0
#define OFF4 1024
#define OFF5 2912
#define BUFN 3168

typedef unsigned long long u64;

// ---------------- scratch (device globals) ----------------------------------
__device__ int g_cell_of[NPTS];
__device__ int g_sorted[NPTS];
__device__ float4 g_pt[2 * NPTS];     // (x0,x1,x2,d0),(d1,d2,-,-) per sorted slot
__device__ int g_count[NC];
__device__ int g_start[NC + 1];
__device__ int g_cursor[NC];
__device__ float g_w2pad[NC * 32 * 36];   // w2 rows padded 33 -> 36
__device__ float g_w5pad[NC * 32 * 4];    // w5 rows padded 3 -> 4

__device__ __forceinline__ int cell_coord(float v) {
    float f = v / 0.1875f + 8.0f;
    int c = (int)f;
    if (c < 0) c = 0;
    if (c > 15) c = 15;
    return c;
}

// ---------------- prep: pad w2 rows 33->36, w5 rows 3->4 --------------------
__global__ void k_pad2(const float* __restrict__ w2) {
    int t = blockIdx.x * blockDim.x + threadIdx.x;
    if (t >= NC * 1056) return;
    int cell = t / 1056;
    int i = t - cell * 1056;
    int r = i / 33, c = i - r * 33;
    g_w2pad[cell * 1152 + r * 36 + c] = w2[t];
}
__global__ void k_pad5(const float* __restrict__ w5) {
    int t = blockIdx.x * blockDim.x + threadIdx.x;
    if (t >= NC * 96) return;
    int cell = t / 96;
    int i = t - cell * 96;
    int r = i / 3, c = i - r * 3;
    g_w5pad[cell * 128 + r * 4 + c] = w5[t];
}

// ---------------- pass 1: cell index + histogram ----------------------------
__global__ void k_hist(const float* __restrict__ x) {
    int p = blockIdx.x * blockDim.x + threadIdx.x;
    if (p >= NPTS) return;
    int c0 = cell_coord(x[3 * p + 0]);
    int c1 = cell_coord(x[3 * p + 1]);
    int c2 = cell_coord(x[3 * p + 2]);
    int cell = (c0 * 16 + c1) * 16 + c2;
    g_cell_of[p] = cell;
    atomicAdd(&g_count[cell], 1);
}

// ---------------- pass 2: exclusive scan + reset counts (1 block) -----------
__global__ void k_scan() {
    __shared__ int s[1024];
    int t = threadIdx.x;
    int b = t * 4;
    int c0 = g_count[b + 0];
    int c1 = g_count[b + 1];
    int c2 = g_count[b + 2];
    int c3 = g_count[b + 3];
    g_count[b + 0] = 0; g_count[b + 1] = 0; g_count[b + 2] = 0; g_count[b + 3] = 0;
    int sum = c0 + c1 + c2 + c3;
    s[t] = sum;
    __syncthreads();
    #pragma unroll
    for (int off = 1; off < 1024; off <<= 1) {
        int v = (t >= off) ? s[t - off] : 0;
        __syncthreads();
        s[t] += v;
        __syncthreads();
    }
    int excl = s[t] - sum;
    g_start[b + 0] = excl;
    g_start[b + 1] = excl + c0;
    g_start[b + 2] = excl + c0 + c1;
    g_start[b + 3] = excl + c0 + c1 + c2;
    if (t == 1023) g_start[NC] = s[1023];
}

// ---------------- pass 3: scatter indices + staged point data ---------------
__global__ void k_scatter(const float* __restrict__ x, const float* __restrict__ d) {
    int p = blockIdx.x * blockDim.x + threadIdx.x;
    if (p >= NPTS) return;
    int cell = g_cell_of[p];
    int pos = g_start[cell] + atomicAdd(&g_cursor[cell], 1);
    g_sorted[pos] = p;
    float x0 = x[3 * p + 0], x1 = x[3 * p + 1], x2 = x[3 * p + 2];
    float d0 = d[3 * p + 0], d1 = d[3 * p + 1], d2 = d[3 * p + 2];
    g_pt[2 * pos + 0] = make_float4(x0, x1, x2, d0);
    g_pt[2 * pos + 1] = make_float4(d1, d2, 0.0f, 0.0f);
}

// ---------------- fast sincos: Cody-Waite reduction + MUFU ------------------
__device__ __forceinline__ void fsincos(float a, float& sn, float& cs) {
    float k = rintf(a * 0.15915493667125702f);
    float r = fmaf(k, -6.2831854820251465f, a);
    r = fmaf(k, 1.7484556000744487e-7f, r);
    sn = __sinf(r);
    cs = __cosf(r);
}

// ---------------- cp.async helpers ------------------------------------------
__device__ __forceinline__ void cpa16(uint32_t saddr, const void* g) {
    asm volatile("cp.async.cg.shared.global [%0], [%1], 16;" :: "r"(saddr), "l"(g));
}
__device__ __forceinline__ void cpa_commit() {
    asm volatile("cp.async.commit_group;");
}
__device__ __forceinline__ void cpa_wait0() {
    asm volatile("cp.async.wait_group 0;");
}
__device__ __forceinline__ void cpa_wait1() {
    asm volatile("cp.async.wait_group 1;");
}

template <int N4>
__device__ __forceinline__ void stage(uint32_t dst, const float4* __restrict__ src, int tid) {
    #pragma unroll
    for (int i = tid; i < N4; i += 32) cpa16(dst + 16u * i, src + i);
}

// ---------------- packed f32x2 primitives -----------------------------------
__device__ __forceinline__ void fma2(u64& a, u64 v, u64 w) {
    asm("fma.rn.f32x2 %0, %1, %2, %0;" : "+l"(a) : "l"(v), "l"(w));
}
__device__ __forceinline__ u64 pk2(float v) {
    u64 r; asm("mov.b64 %0, {%1, %1};" : "=l"(r) : "f"(v)); return r;
}
__device__ __forceinline__ float2 upk(u64 p) {
    float2 f; asm("mov.b64 {%0, %1}, %2;" : "=f"(f.x), "=f"(f.y) : "l"(p)); return f;
}

// feed one scalar input into NP2*2 packed accumulator pairs (NP2 LDS.128 loads)
template <int NP2>
__device__ __forceinline__ void feedp(float v, const float* __restrict__ w, u64* acc) {
    u64 vv = pk2(v);
    const ulonglong2* wv = (const ulonglong2*)w;
    #pragma unroll
    for (int k = 0; k < NP2; k++) {
        ulonglong2 u = wv[k];
        fma2(acc[2 * k + 0], vv, u.x);
        fma2(acc[2 * k + 1], vv, u.y);
    }
}

// ---------------- pass 4: per-cell MLP, streamed weights, packed math -------
__global__ void __launch_bounds__(32, 14) k_mlp(
    const float* __restrict__ w1, const float* __restrict__ b1,
    const float* __restrict__ b2,
    const float* __restrict__ w3, const float* __restrict__ b3,
    const float* __restrict__ w4, const float* __restrict__ b4,
    const float* __restrict__ b5,
    float* __restrict__ out)
{
    int cell = blockIdx.x;
    int tid = threadIdx.x;

    if (tid == 0) g_cursor[cell] = 0;   // reset for next invocation

    int start = g_start[cell];
    int cnt = g_start[cell + 1] - start;
    if (cnt == 0) return;

    __shared__ __align__(16) float sbuf[BUFN];
    __shared__ __align__(16) float sb1[32];
    __shared__ __align__(16) float sb2[36];
    __shared__ __align__(16) float sb3[32];
    __shared__ __align__(16) float sb4[32];
    __shared__ __align__(16) float sb5[4];

    const size_t c = (size_t)cell;
    const float4* w1v = (const float4*)(w1 + c * 2016);
    const float4* w2v = (const float4*)(g_w2pad + c * 1152);
    const float4* w3v = (const float4*)(w3 + c * 1024);
    const float4* w4v = (const float4*)(w4 + c * 1888);
    const float4* w5v = (const float4*)(g_w5pad + c * 128);

    // biases once per block
    sb1[tid] = b1[c * 32 + tid];
    sb3[tid] = b3[c * 32 + tid];
    sb4[tid] = b4[c * 32 + tid];
    sb2[tid] = b2[c * 33 + tid];
    if (tid == 0) sb2[32] = b2[c * 33 + 32];
    if (tid < 3) sb5[tid] = b5[c * 3 + tid];

    uint32_t sb = (uint32_t)__cvta_generic_to_shared(sbuf);

    for (int base = 0; base < cnt; base += 32) {
        int q = base + tid;
        bool active = q < cnt;
        int slot = start + (active ? q : (cnt - 1));

        float4 pa = g_pt[2 * slot + 0];
        float4 pb = g_pt[2 * slot + 1];
        float x0 = pa.x, x1 = pa.y, x2 = pa.z;
        float d0 = pa.w, d1 = pb.x, d2 = pb.y;
        bool mask = (fabsf(x0) < 1.5f) && (fabsf(x1) < 1.5f) && (fabsf(x2) < 1.5f);

        // issue L1 and L2 prefetch
        stage<504>(sb + OFF1 * 4, w1v, tid); cpa_commit();
        stage<288>(sb + OFF2 * 4, w2v, tid); cpa_commit();
        cpa_wait1();
        __syncwarp();

        u64 P[17];          // packed accumulator pairs
        float Asc[33];      // unpacked activations

        // ---- layer 1: encode(x) [63] -> 32, relu ----
        {
            const float* sw1 = sbuf + OFF1;
            const u64* bp = (const u64*)sb1;
            #pragma unroll
            for (int k = 0; k < 16; k++) P[k] = bp[k];
            feedp<8>(x0, sw1 +  0, P);
            feedp<8>(x1, sw1 + 32, P);
            feedp<8>(x2, sw1 + 64, P);
            const float* wp = sw1 + 96;
            float s = 1.0f;
            #pragma unroll
            for (int j = 0; j < 10; j++) {
                float sn0, cs0, sn1, cs1, sn2, cs2;
                fsincos(s * x0, sn0, cs0);
                fsincos(s * x1, sn1, cs1);
                fsincos(s * x2, sn2, cs2);
                feedp<8>(sn0, wp, P); wp += 32;
                feedp<8>(sn1, wp, P); wp += 32;
                feedp<8>(sn2, wp, P); wp += 32;
                feedp<8>(cs0, wp, P); wp += 32;
                feedp<8>(cs1, wp, P); wp += 32;
                feedp<8>(cs2, wp, P); wp += 32;
                s *= 2.0f;
            }
            #pragma unroll
            for (int k = 0; k < 16; k++) {
                float2 f = upk(P[k]);
                Asc[2 * k + 0] = fmaxf(f.x, 0.0f);
                Asc[2 * k + 1] = fmaxf(f.y, 0.0f);
            }
        }

        cpa_wait0(); __syncwarp();
        stage<256>(sb + OFF3 * 4, w3v, tid); cpa_commit();   // prefetch L3

        // ---- layer 2: 32 -> 33 (rows padded to 36), relu; sigma = out[0] ----
        float sigma;
        {
            const float* sw2 = sbuf + OFF2;
            const u64* bp = (const u64*)sb2;
            #pragma unroll
            for (int k = 0; k < 16; k++) P[k] = bp[k];
            float a32 = sb2[32];
            #pragma unroll
            for (int i = 0; i < 32; i++) {
                const float* row = sw2 + i * 36;
                float v = Asc[i];
                feedp<8>(v, row, P);
                a32 = fmaf(v, row[32], a32);
            }
            #pragma unroll
            for (int k = 0; k < 16; k++) {
                float2 f = upk(P[k]);
                Asc[2 * k + 0] = fmaxf(f.x, 0.0f);
                Asc[2 * k + 1] = fmaxf(f.y, 0.0f);
            }
            Asc[32] = fmaxf(a32, 0.0f);
            sigma = Asc[0];
        }

        cpa_wait0(); __syncwarp();
        stage<472>(sb + OFF4 * 4, w4v, tid); cpa_commit();   // prefetch L4

        // ---- layer 3: 32 -> 32, linear (inputs Asc[1..32]) ----
        {
            const float* sw3 = sbuf + OFF3;
            const u64* bp = (const u64*)sb3;
            #pragma unroll
            for (int k = 0; k < 16; k++) P[k] = bp[k];
            #pragma unroll
            for (int i = 0; i < 32; i++) feedp<8>(Asc[i + 1], sw3 + i * 32, P);
            #pragma unroll
            for (int k = 0; k < 16; k++) {
                float2 f = upk(P[k]);
                Asc[2 * k + 0] = f.x;
                Asc[2 * k + 1] = f.y;
            }
        }

        cpa_wait0(); __syncwarp();
        stage<32>(sb + OFF5 * 4, w5v, tid); cpa_commit();    // prefetch L5

        // ---- layer 4: [32 | encode(d) 27] -> 32, relu ----
        {
            const float* sw4 = sbuf + OFF4;
            const u64* bp = (const u64*)sb4;
            #pragma unroll
            for (int k = 0; k < 16; k++) P[k] = bp[k];
            #pragma unroll
            for (int i = 0; i < 32; i++) feedp<8>(Asc[i], sw4 + i * 32, P);
            const float* wp = sw4 + 32 * 32;
            feedp<8>(d0, wp, P); wp += 32;
            feedp<8>(d1, wp, P); wp += 32;
            feedp<8>(d2, wp, P); wp += 32;
            float s = 1.0f;
            #pragma unroll
            for (int j = 0; j < 4; j++) {
                float sn0, cs0, sn1, cs1, sn2, cs2;
                fsincos(s * d0, sn0, cs0);
                fsincos(s * d1, sn1, cs1);
                fsincos(s * d2, sn2, cs2);
                feedp<8>(sn0, wp, P); wp += 32;
                feedp<8>(sn1, wp, P); wp += 32;
                feedp<8>(sn2, wp, P); wp += 32;
                feedp<8>(cs0, wp, P); wp += 32;
                feedp<8>(cs1, wp, P); wp += 32;
                feedp<8>(cs2, wp, P); wp += 32;
                s *= 2.0f;
            }
            #pragma unroll
            for (int k = 0; k < 16; k++) {
                float2 f = upk(P[k]);
                Asc[2 * k + 0] = fmaxf(f.x, 0.0f);
                Asc[2 * k + 1] = fmaxf(f.y, 0.0f);
            }
        }

        cpa_wait0(); __syncwarp();

        // ---- layer 5: 32 -> 3 (rows padded to 4), sigmoid ----
        float r0, r1, r2;
        {
            const float* sw5 = sbuf + OFF5;
            u64 r01;
            asm("mov.b64 %0, {%1, %2};" : "=l"(r01) : "f"(sb5[0]), "f"(sb5[1]));
            r2 = sb5[2];
            const ulonglong2* wv = (const ulonglong2*)sw5;
            #pragma unroll
            for (int i = 0; i < 32; i++) {
                ulonglong2 u = wv[i];
                float v = Asc[i];
                fma2(r01, pk2(v), u.x);
                r2 = fmaf(v, upk(u.y).x, r2);
            }
            float2 f = upk(r01);
            r0 = 1.0f / (1.0f + __expf(-f.x));
            r1 = 1.0f / (1.0f + __expf(-f.y));
            r2 = 1.0f / (1.0f + __expf(-r2));
        }

        if (!mask) { r0 = 0.0f; r1 = 0.0f; r2 = 0.0f; sigma = 0.0f; }

        if (active) {
            int idx = g_sorted[start + q];
            out[3 * idx + 0] = r0;
            out[3 * idx + 1] = r1;
            out[3 * idx + 2] = r2;
            out[3 * NPTS + idx] = sigma;
        }
        __syncwarp();   // all lanes done reading sbuf before next pass restages
    }
}

// ---------------- launch ----------------------------------------------------
extern "C" void kernel_launch(void* const* d_in, const int* in_sizes, int n_in,
                              void* d_out, int out_size) {
    const float* x  = (const float*)d_in[0];
    const float* dd = (const float*)d_in[1];
    const float* w1 = (const float*)d_in[2];
    const float* b1 = (const float*)d_in[3];
    const float* w2 = (const float*)d_in[4];
    const float* b2 = (const float*)d_in[5];
    const float* w3 = (const float*)d_in[6];
    const float* b3 = (const float*)d_in[7];
    const float* w4 = (const float*)d_in[8];
    const float* b4 = (const float*)d_in[9];
    const float* w5 = (const float*)d_in[10];
    const float* b5 = (const float*)d_in[11];
    float* out = (float*)d_out;

    k_pad2<<<(NC * 1056 + 255) / 256, 256>>>(w2);
    k_pad5<<<(NC * 96 + 255) / 256, 256>>>(w5);
    k_hist<<<NPTS / 256, 256>>>(x);
    k_scan<<<1, 1024>>>();
    k_scatter<<<NPTS / 256, 256>>>(x, dd);
    k_mlp<<<NC, 32>>>(w1, b1, b2, w3, b3, w4, b4, b5, out);
}

// round 6
// speedup vs baseline: 2.5084x; 1.4130x over previous
#include <cuda_runtime.h>
#include <math.h>
#include <stdint.h>

#define NPTS 131072
#define NC 4096

// ring-buffer float offsets for streamed layers
#define OFF1 0
#define OFF2 2016
#define OFF3 0
#define OFF4 1024
#define OFF5 2912
#define BUFN 3168

typedef unsigned long long u64;

// ---------------- scratch (device globals) ----------------------------------
__device__ int g_cell_of[NPTS];
__device__ float4 g_pt[2 * NPTS];     // (x0,x1,x2,d0),(d1,d2,idx,-) per sorted slot
__device__ int g_count[NC];
__device__ int g_start[NC + 1];
__device__ int g_cursor[NC];
__device__ float g_w2pad[NC * 32 * 36];   // w2 rows padded 33 -> 36
__device__ float g_w5pad[NC * 32 * 4];    // w5 rows padded 3 -> 4

__device__ __forceinline__ int cell_coord(float v) {
    float f = v / 0.1875f + 8.0f;
    int c = (int)f;
    if (c < 0) c = 0;
    if (c > 15) c = 15;
    return c;
}

// ---------------- prep: pad w2 rows 33->36 and w5 rows 3->4 -----------------
#define PAD2_T (NC * 1056)
#define PAD5_T (NC * 96)
__global__ void k_pad(const float* __restrict__ w2, const float* __restrict__ w5) {
    int t = blockIdx.x * blockDim.x + threadIdx.x;
    if (t < PAD2_T) {
        int cell = t / 1056;
        int i = t - cell * 1056;
        int r = i / 33, c = i - r * 33;
        g_w2pad[cell * 1152 + r * 36 + c] = w2[t];
    } else if (t < PAD2_T + PAD5_T) {
        int u = t - PAD2_T;
        int cell = u / 96;
        int i = u - cell * 96;
        int r = i / 3, c = i - r * 3;
        g_w5pad[cell * 128 + r * 4 + c] = w5[u];
    }
}

// ---------------- pass 1: cell index + histogram (unmasked only) ------------
__global__ void k_hist(const float* __restrict__ x) {
    int p = blockIdx.x * blockDim.x + threadIdx.x;
    if (p >= NPTS) return;
    float x0 = x[3 * p + 0], x1 = x[3 * p + 1], x2 = x[3 * p + 2];
    if (!((fabsf(x0) < 1.5f) && (fabsf(x1) < 1.5f) && (fabsf(x2) < 1.5f))) return;
    int c0 = cell_coord(x0);
    int c1 = cell_coord(x1);
    int c2 = cell_coord(x2);
    int cell = (c0 * 16 + c1) * 16 + c2;
    g_cell_of[p] = cell;
    atomicAdd(&g_count[cell], 1);
}

// ---------------- pass 2: shfl-scan + reset counts (1 block, 1024 thr) ------
__global__ void k_scan() {
    __shared__ int wsum[32];
    int t = threadIdx.x;
    int lane = t & 31, w = t >> 5;
    int b = t * 4;
    int4 cv = *(int4*)&g_count[b];
    *(int4*)&g_count[b] = make_int4(0, 0, 0, 0);
    int sum = cv.x + cv.y + cv.z + cv.w;
    int inc = sum;
    #pragma unroll
    for (int o = 1; o < 32; o <<= 1) {
        int v = __shfl_up_sync(0xFFFFFFFFu, inc, o);
        if (lane >= o) inc += v;
    }
    if (lane == 31) wsum[w] = inc;
    __syncthreads();
    if (w == 0) {
        int v = wsum[lane];
        int i = v;
        #pragma unroll
        for (int o = 1; o < 32; o <<= 1) {
            int u = __shfl_up_sync(0xFFFFFFFFu, i, o);
            if (lane >= o) i += u;
        }
        wsum[lane] = i - v;   // exclusive
    }
    __syncthreads();
    int excl = wsum[w] + inc - sum;
    g_start[b + 0] = excl;
    g_start[b + 1] = excl + cv.x;
    g_start[b + 2] = excl + cv.x + cv.y;
    g_start[b + 3] = excl + cv.x + cv.y + cv.z;
    if (t == 1023) g_start[NC] = excl + sum;
}

// ---------------- pass 3: scatter staged data / zero masked outputs ---------
__global__ void k_scatter(const float* __restrict__ x, const float* __restrict__ d,
                          float* __restrict__ out) {
    int p = blockIdx.x * blockDim.x + threadIdx.x;
    if (p >= NPTS) return;
    float x0 = x[3 * p + 0], x1 = x[3 * p + 1], x2 = x[3 * p + 2];
    bool mask = (fabsf(x0) < 1.5f) && (fabsf(x1) < 1.5f) && (fabsf(x2) < 1.5f);
    if (!mask) {
        out[3 * p + 0] = 0.0f;
        out[3 * p + 1] = 0.0f;
        out[3 * p + 2] = 0.0f;
        out[3 * NPTS + p] = 0.0f;
        return;
    }
    int cell = g_cell_of[p];
    int pos = g_start[cell] + atomicAdd(&g_cursor[cell], 1);
    float d0 = d[3 * p + 0], d1 = d[3 * p + 1], d2 = d[3 * p + 2];
    g_pt[2 * pos + 0] = make_float4(x0, x1, x2, d0);
    g_pt[2 * pos + 1] = make_float4(d1, d2, __int_as_float(p), 0.0f);
}

// ---------------- fast sincos: Cody-Waite reduction + MUFU ------------------
__device__ __forceinline__ void fsincos(float a, float& sn, float& cs) {
    float k = rintf(a * 0.15915493667125702f);
    float r = fmaf(k, -6.2831854820251465f, a);
    r = fmaf(k, 1.7484556000744487e-7f, r);
    sn = __sinf(r);
    cs = __cosf(r);
}

// ---------------- cp.async helpers ------------------------------------------
__device__ __forceinline__ void cpa16(uint32_t saddr, const void* g) {
    asm volatile("cp.async.cg.shared.global [%0], [%1], 16;" :: "r"(saddr), "l"(g));
}
__device__ __forceinline__ void cpa_commit() {
    asm volatile("cp.async.commit_group;");
}
__device__ __forceinline__ void cpa_wait0() {
    asm volatile("cp.async.wait_group 0;");
}
__device__ __forceinline__ void cpa_wait1() {
    asm volatile("cp.async.wait_group 1;");
}

template <int N4>
__device__ __forceinline__ void stage(uint32_t dst, const float4* __restrict__ src, int tid) {
    #pragma unroll
    for (int i = tid; i < N4; i += 32) cpa16(dst + 16u * i, src + i);
}

// ---------------- packed f32x2 primitives -----------------------------------
__device__ __forceinline__ void fma2(u64& a, u64 v, u64 w) {
    asm("fma.rn.f32x2 %0, %1, %2, %0;" : "+l"(a) : "l"(v), "l"(w));
}
__device__ __forceinline__ u64 pk2(float v) {
    u64 r; asm("mov.b64 %0, {%1, %1};" : "=l"(r) : "f"(v)); return r;
}
__device__ __forceinline__ float2 upk(u64 p) {
    float2 f; asm("mov.b64 {%0, %1}, %2;" : "=f"(f.x), "=f"(f.y) : "l"(p)); return f;
}

template <int NP2>
__device__ __forceinline__ void feedp(float v, const float* __restrict__ w, u64* acc) {
    u64 vv = pk2(v);
    const ulonglong2* wv = (const ulonglong2*)w;
    #pragma unroll
    for (int k = 0; k < NP2; k++) {
        ulonglong2 u = wv[k];
        fma2(acc[2 * k + 0], vv, u.x);
        fma2(acc[2 * k + 1], vv, u.y);
    }
}

// ---------------- pass 4: per-cell MLP, streamed weights, packed math -------
__global__ void __launch_bounds__(32, 14) k_mlp(
    const float* __restrict__ w1, const float* __restrict__ b1,
    const float* __restrict__ b2,
    const float* __restrict__ w3, const float* __restrict__ b3,
    const float* __restrict__ w4, const float* __restrict__ b4,
    const float* __restrict__ b5,
    float* __restrict__ out)
{
    int cell = blockIdx.x;
    int tid = threadIdx.x;

    if (tid == 0) g_cursor[cell] = 0;   // reset for next invocation

    int start = g_start[cell];
    int cnt = g_start[cell + 1] - start;
    if (cnt == 0) return;

    __shared__ __align__(16) float sbuf[BUFN];
    __shared__ __align__(16) float sb1[32];
    __shared__ __align__(16) float sb2[36];
    __shared__ __align__(16) float sb3[32];
    __shared__ __align__(16) float sb4[32];
    __shared__ __align__(16) float sb5[4];

    const size_t c = (size_t)cell;
    const float4* w1v = (const float4*)(w1 + c * 2016);
    const float4* w2v = (const float4*)(g_w2pad + c * 1152);
    const float4* w3v = (const float4*)(w3 + c * 1024);
    const float4* w4v = (const float4*)(w4 + c * 1888);
    const float4* w5v = (const float4*)(g_w5pad + c * 128);

    // biases once per block
    sb1[tid] = b1[c * 32 + tid];
    sb3[tid] = b3[c * 32 + tid];
    sb4[tid] = b4[c * 32 + tid];
    sb2[tid] = b2[c * 33 + tid];
    if (tid == 0) sb2[32] = b2[c * 33 + 32];
    if (tid < 3) sb5[tid] = b5[c * 3 + tid];

    uint32_t sb = (uint32_t)__cvta_generic_to_shared(sbuf);

    for (int base = 0; base < cnt; base += 32) {
        int q = base + tid;
        bool active = q < cnt;
        int slot = start + (active ? q : (cnt - 1));

        float4 pa = g_pt[2 * slot + 0];
        float4 pb = g_pt[2 * slot + 1];
        float x0 = pa.x, x1 = pa.y, x2 = pa.z;
        float d0 = pa.w, d1 = pb.x, d2 = pb.y;
        int idx = __float_as_int(pb.z);

        // issue L1 and L2 prefetch
        stage<504>(sb + OFF1 * 4, w1v, tid); cpa_commit();
        stage<288>(sb + OFF2 * 4, w2v, tid); cpa_commit();
        cpa_wait1();
        __syncwarp();

        u64 P[17];          // packed accumulator pairs
        float Asc[33];      // unpacked activations

        // ---- layer 1: encode(x) [63] -> 32, relu ----
        {
            const float* sw1 = sbuf + OFF1;
            const u64* bp = (const u64*)sb1;
            #pragma unroll
            for (int k = 0; k < 16; k++) P[k] = bp[k];
            feedp<8>(x0, sw1 +  0, P);
            feedp<8>(x1, sw1 + 32, P);
            feedp<8>(x2, sw1 + 64, P);
            const float* wp = sw1 + 96;
            float s = 1.0f;
            #pragma unroll
            for (int j = 0; j < 10; j++) {
                float sn0, cs0, sn1, cs1, sn2, cs2;
                fsincos(s * x0, sn0, cs0);
                fsincos(s * x1, sn1, cs1);
                fsincos(s * x2, sn2, cs2);
                feedp<8>(sn0, wp, P); wp += 32;
                feedp<8>(sn1, wp, P); wp += 32;
                feedp<8>(sn2, wp, P); wp += 32;
                feedp<8>(cs0, wp, P); wp += 32;
                feedp<8>(cs1, wp, P); wp += 32;
                feedp<8>(cs2, wp, P); wp += 32;
                s *= 2.0f;
            }
            #pragma unroll
            for (int k = 0; k < 16; k++) {
                float2 f = upk(P[k]);
                Asc[2 * k + 0] = fmaxf(f.x, 0.0f);
                Asc[2 * k + 1] = fmaxf(f.y, 0.0f);
            }
        }

        cpa_wait0(); __syncwarp();
        stage<256>(sb + OFF3 * 4, w3v, tid); cpa_commit();   // prefetch L3

        // ---- layer 2: 32 -> 33 (rows padded to 36), relu; sigma = out[0] ----
        float sigma;
        {
            const float* sw2 = sbuf + OFF2;
            const u64* bp = (const u64*)sb2;
            #pragma unroll
            for (int k = 0; k < 16; k++) P[k] = bp[k];
            float a32 = sb2[32];
            #pragma unroll
            for (int i = 0; i < 32; i++) {
                const float* row = sw2 + i * 36;
                float v = Asc[i];
                feedp<8>(v, row, P);
                a32 = fmaf(v, row[32], a32);
            }
            #pragma unroll
            for (int k = 0; k < 16; k++) {
                float2 f = upk(P[k]);
                Asc[2 * k + 0] = fmaxf(f.x, 0.0f);
                Asc[2 * k + 1] = fmaxf(f.y, 0.0f);
            }
            Asc[32] = fmaxf(a32, 0.0f);
            sigma = Asc[0];
        }

        cpa_wait0(); __syncwarp();
        stage<472>(sb + OFF4 * 4, w4v, tid); cpa_commit();   // prefetch L4

        // ---- layer 3: 32 -> 32, linear (inputs Asc[1..32]) ----
        {
            const float* sw3 = sbuf + OFF3;
            const u64* bp = (const u64*)sb3;
            #pragma unroll
            for (int k = 0; k < 16; k++) P[k] = bp[k];
            #pragma unroll
            for (int i = 0; i < 32; i++) feedp<8>(Asc[i + 1], sw3 + i * 32, P);
            #pragma unroll
            for (int k = 0; k < 16; k++) {
                float2 f = upk(P[k]);
                Asc[2 * k + 0] = f.x;
                Asc[2 * k + 1] = f.y;
            }
        }

        cpa_wait0(); __syncwarp();
        stage<32>(sb + OFF5 * 4, w5v, tid); cpa_commit();    // prefetch L5

        // ---- layer 4: [32 | encode(d) 27] -> 32, relu ----
        {
            const float* sw4 = sbuf + OFF4;
            const u64* bp = (const u64*)sb4;
            #pragma unroll
            for (int k = 0; k < 16; k++) P[k] = bp[k];
            #pragma unroll
            for (int i = 0; i < 32; i++) feedp<8>(Asc[i], sw4 + i * 32, P);
            const float* wp = sw4 + 32 * 32;
            feedp<8>(d0, wp, P); wp += 32;
            feedp<8>(d1, wp, P); wp += 32;
            feedp<8>(d2, wp, P); wp += 32;
            float s = 1.0f;
            #pragma unroll
            for (int j = 0; j < 4; j++) {
                float sn0, cs0, sn1, cs1, sn2, cs2;
                fsincos(s * d0, sn0, cs0);
                fsincos(s * d1, sn1, cs1);
                fsincos(s * d2, sn2, cs2);
                feedp<8>(sn0, wp, P); wp += 32;
                feedp<8>(sn1, wp, P); wp += 32;
                feedp<8>(sn2, wp, P); wp += 32;
                feedp<8>(cs0, wp, P); wp += 32;
                feedp<8>(cs1, wp, P); wp += 32;
                feedp<8>(cs2, wp, P); wp += 32;
                s *= 2.0f;
            }
            #pragma unroll
            for (int k = 0; k < 16; k++) {
                float2 f = upk(P[k]);
                Asc[2 * k + 0] = fmaxf(f.x, 0.0f);
                Asc[2 * k + 1] = fmaxf(f.y, 0.0f);
            }
        }

        cpa_wait0(); __syncwarp();

        // ---- layer 5: 32 -> 3 (rows padded to 4), sigmoid ----
        float r0, r1, r2;
        {
            const float* sw5 = sbuf + OFF5;
            u64 r01;
            asm("mov.b64 %0, {%1, %2};" : "=l"(r01) : "f"(sb5[0]), "f"(sb5[1]));
            r2 = sb5[2];
            const ulonglong2* wv = (const ulonglong2*)sw5;
            #pragma unroll
            for (int i = 0; i < 32; i++) {
                ulonglong2 u = wv[i];
                float v = Asc[i];
                fma2(r01, pk2(v), u.x);
                r2 = fmaf(v, upk(u.y).x, r2);
            }
            float2 f = upk(r01);
            r0 = 1.0f / (1.0f + __expf(-f.x));
            r1 = 1.0f / (1.0f + __expf(-f.y));
            r2 = 1.0f / (1.0f + __expf(-r2));
        }

        if (active) {
            out[3 * idx + 0] = r0;
            out[3 * idx + 1] = r1;
            out[3 * idx + 2] = r2;
            out[3 * NPTS + idx] = sigma;
        }
        __syncwarp();   // all lanes done reading sbuf before next pass restages
    }
}

// ---------------- launch ----------------------------------------------------
extern "C" void kernel_launch(void* const* d_in, const int* in_sizes, int n_in,
                              void* d_out, int out_size) {
    const float* x  = (const float*)d_in[0];
    const float* dd = (const float*)d_in[1];
    const float* w1 = (const float*)d_in[2];
    const float* b1 = (const float*)d_in[3];
    const float* w2 = (const float*)d_in[4];
    const float* b2 = (const float*)d_in[5];
    const float* w3 = (const float*)d_in[6];
    const float* b3 = (const float*)d_in[7];
    const float* w4 = (const float*)d_in[8];
    const float* b4 = (const float*)d_in[9];
    const float* w5 = (const float*)d_in[10];
    const float* b5 = (const float*)d_in[11];
    float* out = (float*)d_out;

    k_pad<<<(PAD2_T + PAD5_T + 255) / 256, 256>>>(w2, w5);
    k_hist<<<NPTS / 256, 256>>>(x);
    k_scan<<<1, 1024>>>();
    k_scatter<<<NPTS / 256, 256>>>(x, dd, out);
    k_mlp<<<NC, 32>>>(w1, b1, b2, w3, b3, w4, b4, b5, out);
}

// round 7
// speedup vs baseline: 2.7738x; 1.1058x over previous
#include <cuda_runtime.h>
#include <math.h>
#include <stdint.h>

#define NPTS 131072
#define NC 4096
#define MAXPASS 8192

// ring-buffer float offsets for streamed layers
#define OFF1 0
#define OFF2 2016
#define OFF3 0
#define OFF4 1024
#define OFF5 2912
#define BUFN 3168

typedef unsigned long long u64;

// ---------------- scratch (device globals) ----------------------------------
__device__ int g_cell_of[NPTS];
__device__ float4 g_pt[2 * NPTS];     // (x0,x1,x2,d0),(d1,d2,idx,-) per sorted slot
__device__ int g_count[NC];
__device__ int g_start[NC + 1];
__device__ int g_cursor[NC];
__device__ int g_npass;
__device__ int2 g_pass[MAXPASS];      // x = slot start, y = cell | (len<<16)
__device__ float g_w2pad[NC * 32 * 36];   // w2 rows padded 33 -> 36
__device__ float g_w5pad[NC * 32 * 4];    // w5 rows padded 3 -> 4

__device__ __forceinline__ int cell_coord(float v) {
    float f = v / 0.1875f + 8.0f;
    int c = (int)f;
    if (c < 0) c = 0;
    if (c > 15) c = 15;
    return c;
}

// ---------------- prep: pad w2 rows 33->36 and w5 rows 3->4 -----------------
#define PAD2_T (NC * 1056)
#define PAD5_T (NC * 96)
__global__ void k_pad(const float* __restrict__ w2, const float* __restrict__ w5) {
    int t = blockIdx.x * blockDim.x + threadIdx.x;
    if (t < PAD2_T) {
        int cell = t / 1056;
        int i = t - cell * 1056;
        int r = i / 33, c = i - r * 33;
        g_w2pad[cell * 1152 + r * 36 + c] = w2[t];
    } else if (t < PAD2_T + PAD5_T) {
        int u = t - PAD2_T;
        int cell = u / 96;
        int i = u - cell * 96;
        int r = i / 3, c = i - r * 3;
        g_w5pad[cell * 128 + r * 4 + c] = w5[u];
    }
}

// ---------------- pass 1: cell index + histogram (unmasked only) ------------
__global__ void k_hist(const float* __restrict__ x) {
    int p = blockIdx.x * blockDim.x + threadIdx.x;
    if (p >= NPTS) return;
    float x0 = x[3 * p + 0], x1 = x[3 * p + 1], x2 = x[3 * p + 2];
    if (!((fabsf(x0) < 1.5f) && (fabsf(x1) < 1.5f) && (fabsf(x2) < 1.5f))) return;
    int c0 = cell_coord(x0);
    int c1 = cell_coord(x1);
    int c2 = cell_coord(x2);
    int cell = (c0 * 16 + c1) * 16 + c2;
    g_cell_of[p] = cell;
    atomicAdd(&g_count[cell], 1);
}

// ---------------- pass 2: shfl-scan + reset counts (1 block, 1024 thr) ------
__global__ void k_scan() {
    __shared__ int wsum[32];
    int t = threadIdx.x;
    int lane = t & 31, w = t >> 5;
    if (t == 0) g_npass = 0;
    int b = t * 4;
    int4 cv = *(int4*)&g_count[b];
    *(int4*)&g_count[b] = make_int4(0, 0, 0, 0);
    int sum = cv.x + cv.y + cv.z + cv.w;
    int inc = sum;
    #pragma unroll
    for (int o = 1; o < 32; o <<= 1) {
        int v = __shfl_up_sync(0xFFFFFFFFu, inc, o);
        if (lane >= o) inc += v;
    }
    if (lane == 31) wsum[w] = inc;
    __syncthreads();
    if (w == 0) {
        int v = wsum[lane];
        int i = v;
        #pragma unroll
        for (int o = 1; o < 32; o <<= 1) {
            int u = __shfl_up_sync(0xFFFFFFFFu, i, o);
            if (lane >= o) i += u;
        }
        wsum[lane] = i - v;   // exclusive
    }
    __syncthreads();
    int excl = wsum[w] + inc - sum;
    g_start[b + 0] = excl;
    g_start[b + 1] = excl + cv.x;
    g_start[b + 2] = excl + cv.x + cv.y;
    g_start[b + 3] = excl + cv.x + cv.y + cv.z;
    if (t == 1023) g_start[NC] = excl + sum;
}

// ---------------- pass 2b: build flattened pass list ------------------------
__global__ void k_passes() {
    int c = blockIdx.x * blockDim.x + threadIdx.x;
    if (c >= NC) return;
    g_cursor[c] = 0;
    int s = g_start[c];
    int cnt = g_start[c + 1] - s;
    if (cnt == 0) return;
    int np = (cnt + 31) >> 5;
    int base = atomicAdd(&g_npass, np);
    for (int k = 0; k < np; k++) {
        int len = min(32, cnt - 32 * k);
        g_pass[base + k] = make_int2(s + 32 * k, c | (len << 16));
    }
}

// ---------------- pass 3: scatter staged data / zero masked outputs ---------
__global__ void k_scatter(const float* __restrict__ x, const float* __restrict__ d,
                          float* __restrict__ out) {
    int p = blockIdx.x * blockDim.x + threadIdx.x;
    if (p >= NPTS) return;
    float x0 = x[3 * p + 0], x1 = x[3 * p + 1], x2 = x[3 * p + 2];
    bool mask = (fabsf(x0) < 1.5f) && (fabsf(x1) < 1.5f) && (fabsf(x2) < 1.5f);
    if (!mask) {
        out[3 * p + 0] = 0.0f;
        out[3 * p + 1] = 0.0f;
        out[3 * p + 2] = 0.0f;
        out[3 * NPTS + p] = 0.0f;
        return;
    }
    int cell = g_cell_of[p];
    int pos = g_start[cell] + atomicAdd(&g_cursor[cell], 1);
    float d0 = d[3 * p + 0], d1 = d[3 * p + 1], d2 = d[3 * p + 2];
    g_pt[2 * pos + 0] = make_float4(x0, x1, x2, d0);
    g_pt[2 * pos + 1] = make_float4(d1, d2, __int_as_float(p), 0.0f);
}

// ---------------- fast sincos: Cody-Waite reduction + MUFU ------------------
__device__ __forceinline__ void fsincos(float a, float& sn, float& cs) {
    float k = rintf(a * 0.15915493667125702f);
    float r = fmaf(k, -6.2831854820251465f, a);
    r = fmaf(k, 1.7484556000744487e-7f, r);
    sn = __sinf(r);
    cs = __cosf(r);
}

// ---------------- cp.async helpers ------------------------------------------
__device__ __forceinline__ void cpa16(uint32_t saddr, const void* g) {
    asm volatile("cp.async.cg.shared.global [%0], [%1], 16;" :: "r"(saddr), "l"(g));
}
__device__ __forceinline__ void cpa_commit() {
    asm volatile("cp.async.commit_group;");
}
__device__ __forceinline__ void cpa_wait0() {
    asm volatile("cp.async.wait_group 0;");
}
__device__ __forceinline__ void cpa_wait1() {
    asm volatile("cp.async.wait_group 1;");
}

template <int N4>
__device__ __forceinline__ void stage(uint32_t dst, const float4* __restrict__ src, int tid) {
    #pragma unroll
    for (int i = tid; i < N4; i += 32) cpa16(dst + 16u * i, src + i);
}

// ---------------- packed f32x2 primitives -----------------------------------
__device__ __forceinline__ void fma2(u64& a, u64 v, u64 w) {
    asm("fma.rn.f32x2 %0, %1, %2, %0;" : "+l"(a) : "l"(v), "l"(w));
}
__device__ __forceinline__ u64 pk2(float v) {
    u64 r; asm("mov.b64 %0, {%1, %1};" : "=l"(r) : "f"(v)); return r;
}
__device__ __forceinline__ float2 upk(u64 p) {
    float2 f; asm("mov.b64 {%0, %1}, %2;" : "=f"(f.x), "=f"(f.y) : "l"(p)); return f;
}

template <int NP2>
__device__ __forceinline__ void feedp(float v, const float* __restrict__ w, u64* acc) {
    u64 vv = pk2(v);
    const ulonglong2* wv = (const ulonglong2*)w;
    #pragma unroll
    for (int k = 0; k < NP2; k++) {
        ulonglong2 u = wv[k];
        fma2(acc[2 * k + 0], vv, u.x);
        fma2(acc[2 * k + 1], vv, u.y);
    }
}

// ---------------- pass 4: one block = one 32-point pass of one cell ---------
__global__ void __launch_bounds__(32, 16) k_mlp(
    const float* __restrict__ w1, const float* __restrict__ b1,
    const float* __restrict__ b2,
    const float* __restrict__ w3, const float* __restrict__ b3,
    const float* __restrict__ w4, const float* __restrict__ b4,
    const float* __restrict__ b5,
    float* __restrict__ out)
{
    int pid = blockIdx.x;
    if (pid >= g_npass) return;
    int2 pe = g_pass[pid];
    int slot0 = pe.x;
    int cell = pe.y & 0xFFFF;
    int len = pe.y >> 16;
    int tid = threadIdx.x;

    __shared__ __align__(16) float sbuf[BUFN];
    __shared__ __align__(16) float sb1[32];
    __shared__ __align__(16) float sb2[36];
    __shared__ __align__(16) float sb3[32];
    __shared__ __align__(16) float sb4[32];
    __shared__ __align__(16) float sb5[4];

    const size_t c = (size_t)cell;
    const float4* w1v = (const float4*)(w1 + c * 2016);
    const float4* w2v = (const float4*)(g_w2pad + c * 1152);
    const float4* w3v = (const float4*)(w3 + c * 1024);
    const float4* w4v = (const float4*)(w4 + c * 1888);
    const float4* w5v = (const float4*)(g_w5pad + c * 128);

    uint32_t sb = (uint32_t)__cvta_generic_to_shared(sbuf);

    // issue L1 and L2 prefetch immediately
    stage<504>(sb + OFF1 * 4, w1v, tid); cpa_commit();
    stage<288>(sb + OFF2 * 4, w2v, tid); cpa_commit();

    // biases (regular LDG/STS, overlap with cp.async)
    sb1[tid] = b1[c * 32 + tid];
    sb3[tid] = b3[c * 32 + tid];
    sb4[tid] = b4[c * 32 + tid];
    sb2[tid] = b2[c * 33 + tid];
    if (tid == 0) sb2[32] = b2[c * 33 + 32];
    if (tid < 3) sb5[tid] = b5[c * 3 + tid];

    bool active = tid < len;
    int slot = slot0 + (active ? tid : (len - 1));
    float4 pa = g_pt[2 * slot + 0];
    float4 pb = g_pt[2 * slot + 1];
    float x0 = pa.x, x1 = pa.y, x2 = pa.z;
    float d0 = pa.w, d1 = pb.x, d2 = pb.y;
    int idx = __float_as_int(pb.z);

    cpa_wait1();
    __syncwarp();

    u64 P[17];          // packed accumulator pairs
    float Asc[33];      // unpacked activations

    // ---- layer 1: encode(x) [63] -> 32, relu ----
    {
        const float* sw1 = sbuf + OFF1;
        const u64* bp = (const u64*)sb1;
        #pragma unroll
        for (int k = 0; k < 16; k++) P[k] = bp[k];
        feedp<8>(x0, sw1 +  0, P);
        feedp<8>(x1, sw1 + 32, P);
        feedp<8>(x2, sw1 + 64, P);
        const float* wp = sw1 + 96;
        float s = 1.0f;
        #pragma unroll
        for (int j = 0; j < 10; j++) {
            float sn0, cs0, sn1, cs1, sn2, cs2;
            fsincos(s * x0, sn0, cs0);
            fsincos(s * x1, sn1, cs1);
            fsincos(s * x2, sn2, cs2);
            feedp<8>(sn0, wp, P); wp += 32;
            feedp<8>(sn1, wp, P); wp += 32;
            feedp<8>(sn2, wp, P); wp += 32;
            feedp<8>(cs0, wp, P); wp += 32;
            feedp<8>(cs1, wp, P); wp += 32;
            feedp<8>(cs2, wp, P); wp += 32;
            s *= 2.0f;
        }
        #pragma unroll
        for (int k = 0; k < 16; k++) {
            float2 f = upk(P[k]);
            Asc[2 * k + 0] = fmaxf(f.x, 0.0f);
            Asc[2 * k + 1] = fmaxf(f.y, 0.0f);
        }
    }

    cpa_wait0(); __syncwarp();
    stage<256>(sb + OFF3 * 4, w3v, tid); cpa_commit();   // prefetch L3

    // ---- layer 2: 32 -> 33 (rows padded to 36), relu; sigma = out[0] ----
    float sigma;
    {
        const float* sw2 = sbuf + OFF2;
        const u64* bp = (const u64*)sb2;
        #pragma unroll
        for (int k = 0; k < 16; k++) P[k] = bp[k];
        float a32 = sb2[32];
        #pragma unroll
        for (int i = 0; i < 32; i++) {
            const float* row = sw2 + i * 36;
            float v = Asc[i];
            feedp<8>(v, row, P);
            a32 = fmaf(v, row[32], a32);
        }
        #pragma unroll
        for (int k = 0; k < 16; k++) {
            float2 f = upk(P[k]);
            Asc[2 * k + 0] = fmaxf(f.x, 0.0f);
            Asc[2 * k + 1] = fmaxf(f.y, 0.0f);
        }
        Asc[32] = fmaxf(a32, 0.0f);
        sigma = Asc[0];
    }

    cpa_wait0(); __syncwarp();
    stage<472>(sb + OFF4 * 4, w4v, tid); cpa_commit();   // prefetch L4

    // ---- layer 3: 32 -> 32, linear (inputs Asc[1..32]) ----
    {
        const float* sw3 = sbuf + OFF3;
        const u64* bp = (const u64*)sb3;
        #pragma unroll
        for (int k = 0; k < 16; k++) P[k] = bp[k];
        #pragma unroll
        for (int i = 0; i < 32; i++) feedp<8>(Asc[i + 1], sw3 + i * 32, P);
        #pragma unroll
        for (int k = 0; k < 16; k++) {
            float2 f = upk(P[k]);
            Asc[2 * k + 0] = f.x;
            Asc[2 * k + 1] = f.y;
        }
    }

    cpa_wait0(); __syncwarp();
    stage<32>(sb + OFF5 * 4, w5v, tid); cpa_commit();    // prefetch L5

    // ---- layer 4: [32 | encode(d) 27] -> 32, relu ----
    {
        const float* sw4 = sbuf + OFF4;
        const u64* bp = (const u64*)sb4;
        #pragma unroll
        for (int k = 0; k < 16; k++) P[k] = bp[k];
        #pragma unroll
        for (int i = 0; i < 32; i++) feedp<8>(Asc[i], sw4 + i * 32, P);
        const float* wp = sw4 + 32 * 32;
        feedp<8>(d0, wp, P); wp += 32;
        feedp<8>(d1, wp, P); wp += 32;
        feedp<8>(d2, wp, P); wp += 32;
        float s = 1.0f;
        #pragma unroll
        for (int j = 0; j < 4; j++) {
            float sn0, cs0, sn1, cs1, sn2, cs2;
            fsincos(s * d0, sn0, cs0);
            fsincos(s * d1, sn1, cs1);
            fsincos(s * d2, sn2, cs2);
            feedp<8>(sn0, wp, P); wp += 32;
            feedp<8>(sn1, wp, P); wp += 32;
            feedp<8>(sn2, wp, P); wp += 32;
            feedp<8>(cs0, wp, P); wp += 32;
            feedp<8>(cs1, wp, P); wp += 32;
            feedp<8>(cs2, wp, P); wp += 32;
            s *= 2.0f;
        }
        #pragma unroll
        for (int k = 0; k < 16; k++) {
            float2 f = upk(P[k]);
            Asc[2 * k + 0] = fmaxf(f.x, 0.0f);
            Asc[2 * k + 1] = fmaxf(f.y, 0.0f);
        }
    }

    cpa_wait0(); __syncwarp();

    // ---- layer 5: 32 -> 3 (rows padded to 4), sigmoid ----
    float r0, r1, r2;
    {
        const float* sw5 = sbuf + OFF5;
        u64 r01;
        asm("mov.b64 %0, {%1, %2};" : "=l"(r01) : "f"(sb5[0]), "f"(sb5[1]));
        r2 = sb5[2];
        const ulonglong2* wv = (const ulonglong2*)sw5;
        #pragma unroll
        for (int i = 0; i < 32; i++) {
            ulonglong2 u = wv[i];
            float v = Asc[i];
            fma2(r01, pk2(v), u.x);
            r2 = fmaf(v, upk(u.y).x, r2);
        }
        float2 f = upk(r01);
        r0 = 1.0f / (1.0f + __expf(-f.x));
        r1 = 1.0f / (1.0f + __expf(-f.y));
        r2 = 1.0f / (1.0f + __expf(-r2));
    }

    if (active) {
        out[3 * idx + 0] = r0;
        out[3 * idx + 1] = r1;
        out[3 * idx + 2] = r2;
        out[3 * NPTS + idx] = sigma;
    }
}

// ---------------- launch ----------------------------------------------------
extern "C" void kernel_launch(void* const* d_in, const int* in_sizes, int n_in,
                              void* d_out, int out_size) {
    const float* x  = (const float*)d_in[0];
    const float* dd = (const float*)d_in[1];
    const float* w1 = (const float*)d_in[2];
    const float* b1 = (const float*)d_in[3];
    const float* w2 = (const float*)d_in[4];
    const float* b2 = (const float*)d_in[5];
    const float* w3 = (const float*)d_in[6];
    const float* b3 = (const float*)d_in[7];
    const float* w4 = (const float*)d_in[8];
    const float* b4 = (const float*)d_in[9];
    const float* w5 = (const float*)d_in[10];
    const float* b5 = (const float*)d_in[11];
    float* out = (float*)d_out;

    k_pad<<<(PAD2_T + PAD5_T + 255) / 256, 256>>>(w2, w5);
    k_hist<<<NPTS / 256, 256>>>(x);
    k_scan<<<1, 1024>>>();
    k_passes<<<NC / 256, 256>>>();
    k_scatter<<<NPTS / 256, 256>>>(x, dd, out);
    k_mlp<<<MAXPASS, 32>>>(w1, b1, b2, w3, b3, w4, b4, b5, out);
}